// round 9
// baseline (speedup 1.0000x reference)
#include <cuda_runtime.h>
#include <cuda_bf16.h>
#include <cstdint>

// ============================================================================
// BCQLinear: y = (x[:, in_reorder] @ dequant(qweight))[:, out_reorder]
// M=128, K=N=4096, WBITS=3, GS=OFI=128.
// R9 = R8 with the dequant-constant bug fixed:
//   B holds q' = 2v-8 (EXACT: 16777224 = 2^24+8 is fp32-representable;
//   2^24+7 is not — that was R8's 0.22 rel_err).  q = q' + 1 is compensated
//   analytically in the epilogue:  y = sum_g [ a*S' + (a+b)*Xsum ].
//   A = x split hi+lo bf16, mma.sync.m16n8k16.bf16, fp32 accum.
// ============================================================================

#define M_TOK   128
#define IN_F    4096
#define OUT_F   4096
#define NGRP    32
#define NSPLIT  4            // K-split planes; 8 groups per split
#define NPLANE  4

// Scratch (static __device__ — no allocations)
__device__ uint4    g_xa[NGRP * 8 * 8 * 2 * 32];         // 2 MB  A frags (hi/lo bf16)
__device__ uint32_t g_qnib[NGRP * 32 * 2048];            // 8 MB  nibbles, B-frag order
__device__ float    g_xsum[NGRP * M_TOK];                // 16 KB group row-sums
__device__ float    g_t_part[NPLANE * M_TOK * OUT_F];    // 8 MB  K-split partials
__device__ float    g_t_sum[M_TOK * OUT_F];              // 2 MB  reduced sum

__device__ __forceinline__ uint32_t smem_u32(const void* p) {
    uint32_t a;
    asm("{ .reg .u64 t; cvta.to.shared.u64 t, %1; cvt.u32.u64 %0, t; }"
        : "=r"(a) : "l"(p));
    return a;
}
__device__ __forceinline__ void cp_async16(uint32_t saddr, const void* gptr) {
    asm volatile("cp.async.cg.shared.global [%0], [%1], 16;"
                 :: "r"(saddr), "l"(gptr));
}
#define CP_COMMIT() asm volatile("cp.async.commit_group;" ::: "memory")
#define CP_WAIT0()  asm volatile("cp.async.wait_group 0;" ::: "memory")

// spread 8 bits so bit t lands at bit 4t
__device__ __forceinline__ uint32_t spread8(uint32_t x) {
    x = (x | (x << 12)) & 0x000F000Fu;
    x = (x | (x << 6))  & 0x03030303u;
    x = (x | (x << 3))  & 0x11111111u;
    return x;
}
// nibble v (bits [shv,shv+4)) -> float q' = 2v-8 (EXACT):
//   as_float(0x4B800000|v) = 2^24 + 2v;  16777224.f = 2^24+8 (representable).
__device__ __forceinline__ float nib2q(uint32_t w, int shv) {
    return __uint_as_float(((w >> shv) & 0xFu) | 0x4B800000u) - 16777224.f;
}
// pack two floats -> bf16x2 reg: upper half = f_hi, lower half = f_lo
__device__ __forceinline__ uint32_t bf16x2(float f_hi, float f_lo) {
    uint32_t d;
    asm("cvt.rn.bf16x2.f32 %0, %1, %2;" : "=r"(d) : "f"(f_hi), "f"(f_lo));
    return d;
}

// ---------------------------------------------------------------------------
// Kernel 1: gather x[:, in_reorder], split into hi/lo bf16, A-frag layout.
// m16n8k16 A frag: reg0={(r,k0),(r,k1)} reg1={r+8,k0..1} reg2={r,k8..9} reg3={r+8,...}
// Layout: g_xa[ (((g*8+ks)*8+mtile)*2+hl)*32 + lane ]
// ---------------------------------------------------------------------------
__global__ __launch_bounds__(256)
void prep_x_kernel(const float* __restrict__ x, const int* __restrict__ in_reorder) {
    const int t    = blockIdx.x * 256 + threadIdx.x;     // 65536 threads
    const int lane = t & 31;
    const int mt   = (t >> 5) & 7;
    const int ks   = (t >> 8) & 7;
    const int g    = t >> 11;
    const int r0   = mt * 16 + (lane >> 2);
    const int kb   = g * 128 + ks * 16 + (lane & 3) * 2;
    const int kk[4] = { kb, kb + 1, kb + 8, kb + 9 };
    uint32_t hi[4], lo[4];
    #pragma unroll
    for (int j = 0; j < 4; j++) {
        const int p = __ldg(&in_reorder[kk[j]]);
        const float va = x[ r0      * IN_F + p];
        const float vb = x[(r0 + 8) * IN_F + p];
        const __nv_bfloat16 ha = __float2bfloat16(va);
        const __nv_bfloat16 hb = __float2bfloat16(vb);
        const __nv_bfloat16 la = __float2bfloat16(va - __bfloat162float(ha));
        const __nv_bfloat16 lb = __float2bfloat16(vb - __bfloat162float(hb));
        const int reg = (j >> 1) * 2;
        if ((j & 1) == 0) {
            hi[reg]     = (uint32_t)__bfloat16_as_ushort(ha);
            hi[reg + 1] = (uint32_t)__bfloat16_as_ushort(hb);
            lo[reg]     = (uint32_t)__bfloat16_as_ushort(la);
            lo[reg + 1] = (uint32_t)__bfloat16_as_ushort(lb);
        } else {
            hi[reg]     |= (uint32_t)__bfloat16_as_ushort(ha) << 16;
            hi[reg + 1] |= (uint32_t)__bfloat16_as_ushort(hb) << 16;
            lo[reg]     |= (uint32_t)__bfloat16_as_ushort(la) << 16;
            lo[reg + 1] |= (uint32_t)__bfloat16_as_ushort(lb) << 16;
        }
    }
    const int base = ((g * 8 + ks) * 8 + mt) * 2;
    g_xa[(base + 0) * 32 + lane] = make_uint4(hi[0], hi[1], hi[2], hi[3]);
    g_xa[(base + 1) * 32 + lane] = make_uint4(lo[0], lo[1], lo[2], lo[3]);
}

// ---------------------------------------------------------------------------
// Kernel 2: Xsum[g][m] = sum_{k in group g} x[m][in_reorder[k]]
// ---------------------------------------------------------------------------
__global__ __launch_bounds__(256)
void xsum_kernel(const float* __restrict__ x, const int* __restrict__ in_reorder) {
    const int m    = blockIdx.x;
    const int tid  = threadIdx.x;
    const int g    = tid >> 3;
    const int part = tid & 7;
    float s = 0.f;
    #pragma unroll
    for (int j = 0; j < 16; j++)
        s += x[m * IN_F + __ldg(&in_reorder[g * 128 + part * 16 + j])];
    s += __shfl_xor_sync(0xffffffffu, s, 1);
    s += __shfl_xor_sync(0xffffffffu, s, 2);
    s += __shfl_xor_sync(0xffffffffu, s, 4);
    if (part == 0) g_xsum[g * 128 + m] = s;
}

// ---------------------------------------------------------------------------
// Kernel 3: repack 3 bit-planes -> nibbles in m16n8k16 B-frag k-order.
// Layout: [tile][ks 8][qq 4][ow 16][it 4], it -> k = {2qq, 2qq+1, 2qq+8, 2qq+9}
// word nibble t = v(i = ks*16+k, o = (ow>>2)*32 + (ow&3)*8 + t)
// ---------------------------------------------------------------------------
__global__ __launch_bounds__(256)
void repack_kernel(const int* __restrict__ qweight, const int* __restrict__ offset) {
    const int t    = blockIdx.x * 256 + threadIdx.x;     // 2097152 threads
    const int it   = t & 3;
    const int ow   = (t >> 2) & 15;
    const int qq   = (t >> 6) & 3;
    const int ks   = (t >> 8) & 7;
    const int tile = t >> 11;                            // g*32 + nb
    const int kk   = 2 * qq + (it & 1) + ((it >> 1) << 3);
    const int i    = ks * 16 + kk;
    const int* src = qweight + __ldg(&offset[tile]);
    const int base = i * 4 + (ow >> 2);
    const int sh   = (ow & 3) * 8;
    const uint32_t b0 = ((uint32_t)__ldg(src + base)        >> sh) & 0xFFu;
    const uint32_t b1 = ((uint32_t)__ldg(src + base + 512)  >> sh) & 0xFFu;
    const uint32_t b2 = ((uint32_t)__ldg(src + base + 1024) >> sh) & 0xFFu;
    g_qnib[t] = spread8(b0) | (spread8(b1) << 1) | (spread8(b2) << 2);
}

// ---------------------------------------------------------------------------
// Kernel 4: bf16 split-A GEMM; epilogue accT += a*S' + (a+b)*Xsum.
// grid (32 nb, 8 = mhalf*4+split), 256 thr, 2 CTA/SM, single full wave.
// ---------------------------------------------------------------------------
__global__ __launch_bounds__(256, 2)
void bcq_gemm_kernel(const float* __restrict__ alpha,
                     const float* __restrict__ beta)
{
    __shared__ uint32_t Qsm[2 * 2048];        // double-buffered B nibbles, 16 KB
    const int tid  = threadIdx.x;
    const int lane = tid & 31;
    const int wid  = tid >> 5;
    const int nb = blockIdx.x;
    const int mhalf = blockIdx.y >> 2;
    const int split = blockIdx.y & 3;
    const int wm = wid & 1;
    const int nq = wid >> 1;
    const uint32_t qsm_base = smem_u32(Qsm) + tid * 16;
    const int shv = (lane >> 2) * 4;

    float accT[2][4][4];
    #pragma unroll
    for (int a = 0; a < 2; a++)
        #pragma unroll
        for (int b = 0; b < 4; b++)
            #pragma unroll
            for (int c = 0; c < 4; c++) accT[a][b][c] = 0.f;

    // prologue: group 0 B tile (8 KB = 256 thr x 32 B)
    {
        const uint32_t* src = g_qnib + (size_t)((split * 8) * 32 + nb) * 2048 + tid * 4;
        cp_async16(qsm_base,        src);
        cp_async16(qsm_base + 4096, src + 1024);
        CP_COMMIT();
    }

    for (int gi = 0; gi < 8; gi++) {
        const int g = split * 8 + gi;

        // alpha/beta/Xsum LDGs issued before the cp wait (latency overlap)
        float av[4][2], cv[4][2], xv[2][2];
        #pragma unroll
        for (int nt = 0; nt < 4; nt++) {
            const int col = nb * 128 + nq * 32 + nt * 8 + (lane & 3) * 2;
            av[nt][0] = __ldg(&alpha[g * OUT_F + col]);
            av[nt][1] = __ldg(&alpha[g * OUT_F + col + 1]);
            // q = q' + 1 compensation: coefficient on Xsum is (alpha + beta)
            cv[nt][0] = av[nt][0] + __ldg(&beta[g * OUT_F + col]);
            cv[nt][1] = av[nt][1] + __ldg(&beta[g * OUT_F + col + 1]);
        }
        #pragma unroll
        for (int mt = 0; mt < 2; mt++) {
            const int row = mhalf * 64 + wm * 32 + mt * 16 + (lane >> 2);
            xv[mt][0] = __ldg(&g_xsum[g * 128 + row]);
            xv[mt][1] = __ldg(&g_xsum[g * 128 + row + 8]);
        }

        CP_WAIT0();
        __syncthreads();

        if (gi < 7) {
            const uint32_t* src = g_qnib + (size_t)((g + 1) * 32 + nb) * 2048 + tid * 4;
            const uint32_t d = qsm_base + ((gi + 1) & 1) * 8192;
            cp_async16(d,        src);
            cp_async16(d + 4096, src + 1024);
            CP_COMMIT();
        }

        const uint32_t* Qh = Qsm + (gi & 1) * 2048;

        float accS[2][4][4];
        #pragma unroll
        for (int a = 0; a < 2; a++)
            #pragma unroll
            for (int b = 0; b < 4; b++)
                #pragma unroll
                for (int c = 0; c < 4; c++) accS[a][b][c] = 0.f;

        #pragma unroll 2
        for (int ks = 0; ks < 8; ks++) {
            // --- A frags: hi+lo, 4 x LDG.128 (L2-resident, frag-ordered) ---
            uint32_t Ah[2][4], Al[2][4];
            #pragma unroll
            for (int mt = 0; mt < 2; mt++) {
                const int mtile = mhalf * 4 + wm * 2 + mt;
                const int base = ((g * 8 + ks) * 8 + mtile) * 2;
                const uint4 h = __ldg(&g_xa[(base + 0) * 32 + lane]);
                const uint4 l = __ldg(&g_xa[(base + 1) * 32 + lane]);
                Ah[mt][0] = h.x; Ah[mt][1] = h.y; Ah[mt][2] = h.z; Ah[mt][3] = h.w;
                Al[mt][0] = l.x; Al[mt][1] = l.y; Al[mt][2] = l.z; Al[mt][3] = l.w;
            }

            // --- B frags: q' = 2v-8 exact bf16 (1 LDS.128 per nt) ---
            uint32_t B[4][2];
            #pragma unroll
            for (int nt = 0; nt < 4; nt++) {
                const uint4 w = *(const uint4*)
                    (Qh + (((ks * 4 + (lane & 3)) * 16 + nq * 4 + nt) << 2));
                B[nt][0] = bf16x2(nib2q(w.y, shv), nib2q(w.x, shv)); // {k0,k1}
                B[nt][1] = bf16x2(nib2q(w.w, shv), nib2q(w.z, shv)); // {k8,k9}
            }

            // --- 16 bf16 HMMA per warp per kstep (hi + lo, same acc) ---
            #pragma unroll
            for (int mt = 0; mt < 2; mt++)
                #pragma unroll
                for (int nt = 0; nt < 4; nt++) {
                    asm volatile(
                        "mma.sync.aligned.m16n8k16.row.col.f32.bf16.bf16.f32 "
                        "{%0,%1,%2,%3}, {%4,%5,%6,%7}, {%8,%9}, {%0,%1,%2,%3};"
                        : "+f"(accS[mt][nt][0]), "+f"(accS[mt][nt][1]),
                          "+f"(accS[mt][nt][2]), "+f"(accS[mt][nt][3])
                        : "r"(Ah[mt][0]), "r"(Ah[mt][1]), "r"(Ah[mt][2]), "r"(Ah[mt][3]),
                          "r"(B[nt][0]), "r"(B[nt][1]));
                    asm volatile(
                        "mma.sync.aligned.m16n8k16.row.col.f32.bf16.bf16.f32 "
                        "{%0,%1,%2,%3}, {%4,%5,%6,%7}, {%8,%9}, {%0,%1,%2,%3};"
                        : "+f"(accS[mt][nt][0]), "+f"(accS[mt][nt][1]),
                          "+f"(accS[mt][nt][2]), "+f"(accS[mt][nt][3])
                        : "r"(Al[mt][0]), "r"(Al[mt][1]), "r"(Al[mt][2]), "r"(Al[mt][3]),
                          "r"(B[nt][0]), "r"(B[nt][1]));
                }
        }

        // --- group epilogue: accT += alpha*S' + (alpha+beta)*Xsum ---
        #pragma unroll
        for (int mt = 0; mt < 2; mt++)
            #pragma unroll
            for (int nt = 0; nt < 4; nt++)
                #pragma unroll
                for (int c = 0; c < 4; c++) {
                    const int e = c & 1, h = c >> 1;
                    accT[mt][nt][c] = fmaf(av[nt][e], accS[mt][nt][c],
                                      fmaf(cv[nt][e], xv[mt][h], accT[mt][nt][c]));
                }
    }

    // --- write K-split partials (deterministic) ---
    float* dst = g_t_part + (size_t)split * (M_TOK * OUT_F);
    #pragma unroll
    for (int mt = 0; mt < 2; mt++) {
        const int row0 = mhalf * 64 + wm * 32 + mt * 16 + (lane >> 2);
        #pragma unroll
        for (int nt = 0; nt < 4; nt++) {
            const int col = nb * 128 + nq * 32 + nt * 8 + (lane & 3) * 2;
            *(float2*)&dst[ row0      * OUT_F + col] =
                make_float2(accT[mt][nt][0], accT[mt][nt][1]);
            *(float2*)&dst[(row0 + 8) * OUT_F + col] =
                make_float2(accT[mt][nt][2], accT[mt][nt][3]);
        }
    }
}

// ---------------------------------------------------------------------------
// Kernel 5: reduce 4 planes (coalesced float4)
// ---------------------------------------------------------------------------
__global__ __launch_bounds__(256)
void reduce_kernel() {
    const int i = blockIdx.x * 256 + threadIdx.x;        // 131072 float4s
    const float4* p = (const float4*)g_t_part;
    float4 s = p[i];
    #pragma unroll
    for (int pl = 1; pl < NPLANE; pl++) {
        const float4 t = p[pl * 131072 + i];
        s.x += t.x; s.y += t.y; s.z += t.z; s.w += t.w;
    }
    ((float4*)g_t_sum)[i] = s;
}

// ---------------------------------------------------------------------------
// Kernel 6: output permutation — coalesced writes, 4 independent gathers
// ---------------------------------------------------------------------------
__global__ __launch_bounds__(256)
void permute_kernel(const int* __restrict__ out_reorder, float* __restrict__ y) {
    const int t = blockIdx.x * 256 + threadIdx.x;        // 131072
    const int c = t & 4095;
    const int mq = t >> 12;                              // 0..31
    const int n = __ldg(&out_reorder[c]);
    #pragma unroll
    for (int u = 0; u < 4; u++) {
        const int m = mq * 4 + u;
        y[(size_t)m * OUT_F + c] = g_t_sum[(m << 12) | n];
    }
}

// ---------------------------------------------------------------------------
// Launch
// ---------------------------------------------------------------------------
extern "C" void kernel_launch(void* const* d_in, const int* in_sizes, int n_in,
                              void* d_out, int out_size) {
    const float* x           = (const float*)d_in[0];
    const int*   qweight     = (const int*)  d_in[1];
    const float* alpha       = (const float*)d_in[2];
    const float* beta        = (const float*)d_in[3];
    // d_in[4] = block_bitwidth (uniform 3, unused)
    const int*   offset      = (const int*)  d_in[5];
    const int*   in_reorder  = (const int*)  d_in[6];
    const int*   out_reorder = (const int*)  d_in[7];
    float* y = (float*)d_out;

    prep_x_kernel<<<256, 256>>>(x, in_reorder);
    xsum_kernel<<<128, 256>>>(x, in_reorder);
    repack_kernel<<<8192, 256>>>(qweight, offset);
    bcq_gemm_kernel<<<dim3(32, 8), 256>>>(alpha, beta);
    reduce_kernel<<<512, 256>>>();
    permute_kernel<<<512, 256>>>(out_reorder, y);
}

// round 10
// speedup vs baseline: 1.1630x; 1.1630x over previous
#include <cuda_runtime.h>
#include <cuda_bf16.h>
#include <cstdint>

// ============================================================================
// BCQLinear: y = (x[:, in_reorder] @ dequant(qweight))[:, out_reorder]
// M=128, K=N=4096, WBITS=3, GS=OFI=128.
// R10 = R9 + two L1 fixes (GEMM was L1-bound at 72%, 4-way LDS conflict):
//  (1) B nibble chunks stored bank-swizzled: physical chunk = (chunk + r) & 15
//      -> the 4 r-lanes of a warp hit disjoint bank groups (was 4-way conflict).
//  (2) alpha/beta/Xsum loads moved into the group epilogue -> ~20 fewer live
//      regs in the MMA loop (was pinned at 128 with spills).
// Math unchanged: B = q' = 2v-8 exact bf16, A = x hi+lo bf16,
//   y = sum_g [ a*S' + (a+b)*Xsum ],  mma.sync.m16n8k16.bf16, fp32 accum.
// ============================================================================

#define M_TOK   128
#define IN_F    4096
#define OUT_F   4096
#define NGRP    32
#define NSPLIT  4            // K-split planes; 8 groups per split
#define NPLANE  4

// Scratch (static __device__ — no allocations)
__device__ uint4    g_xa[NGRP * 8 * 8 * 2 * 32];         // 2 MB  A frags (hi/lo bf16)
__device__ uint32_t g_qnib[NGRP * 32 * 2048];            // 8 MB  nibbles (swizzled)
__device__ float    g_xsum[NGRP * M_TOK];                // 16 KB group row-sums
__device__ float    g_t_part[NPLANE * M_TOK * OUT_F];    // 8 MB  K-split partials
__device__ float    g_t_sum[M_TOK * OUT_F];              // 2 MB  reduced sum

__device__ __forceinline__ uint32_t smem_u32(const void* p) {
    uint32_t a;
    asm("{ .reg .u64 t; cvta.to.shared.u64 t, %1; cvt.u32.u64 %0, t; }"
        : "=r"(a) : "l"(p));
    return a;
}
__device__ __forceinline__ void cp_async16(uint32_t saddr, const void* gptr) {
    asm volatile("cp.async.cg.shared.global [%0], [%1], 16;"
                 :: "r"(saddr), "l"(gptr));
}
#define CP_COMMIT() asm volatile("cp.async.commit_group;" ::: "memory")
#define CP_WAIT0()  asm volatile("cp.async.wait_group 0;" ::: "memory")

// spread 8 bits so bit t lands at bit 4t
__device__ __forceinline__ uint32_t spread8(uint32_t x) {
    x = (x | (x << 12)) & 0x000F000Fu;
    x = (x | (x << 6))  & 0x03030303u;
    x = (x | (x << 3))  & 0x11111111u;
    return x;
}
// nibble v (bits [shv,shv+4)) -> float q' = 2v-8 (EXACT; 2^24+8 representable)
__device__ __forceinline__ float nib2q(uint32_t w, int shv) {
    return __uint_as_float(((w >> shv) & 0xFu) | 0x4B800000u) - 16777224.f;
}
// pack two floats -> bf16x2 reg: upper half = f_hi, lower half = f_lo
__device__ __forceinline__ uint32_t bf16x2(float f_hi, float f_lo) {
    uint32_t d;
    asm("cvt.rn.bf16x2.f32 %0, %1, %2;" : "=r"(d) : "f"(f_hi), "f"(f_lo));
    return d;
}

// ---------------------------------------------------------------------------
// Kernel 1: gather x[:, in_reorder], split into hi/lo bf16, A-frag layout.
// Layout: g_xa[ (((g*8+ks)*8+mtile)*2+hl)*32 + lane ]
// ---------------------------------------------------------------------------
__global__ __launch_bounds__(256)
void prep_x_kernel(const float* __restrict__ x, const int* __restrict__ in_reorder) {
    const int t    = blockIdx.x * 256 + threadIdx.x;     // 65536 threads
    const int lane = t & 31;
    const int mt   = (t >> 5) & 7;
    const int ks   = (t >> 8) & 7;
    const int g    = t >> 11;
    const int r0   = mt * 16 + (lane >> 2);
    const int kb   = g * 128 + ks * 16 + (lane & 3) * 2;
    const int kk[4] = { kb, kb + 1, kb + 8, kb + 9 };
    uint32_t hi[4], lo[4];
    #pragma unroll
    for (int j = 0; j < 4; j++) {
        const int p = __ldg(&in_reorder[kk[j]]);
        const float va = x[ r0      * IN_F + p];
        const float vb = x[(r0 + 8) * IN_F + p];
        const __nv_bfloat16 ha = __float2bfloat16(va);
        const __nv_bfloat16 hb = __float2bfloat16(vb);
        const __nv_bfloat16 la = __float2bfloat16(va - __bfloat162float(ha));
        const __nv_bfloat16 lb = __float2bfloat16(vb - __bfloat162float(hb));
        const int reg = (j >> 1) * 2;
        if ((j & 1) == 0) {
            hi[reg]     = (uint32_t)__bfloat16_as_ushort(ha);
            hi[reg + 1] = (uint32_t)__bfloat16_as_ushort(hb);
            lo[reg]     = (uint32_t)__bfloat16_as_ushort(la);
            lo[reg + 1] = (uint32_t)__bfloat16_as_ushort(lb);
        } else {
            hi[reg]     |= (uint32_t)__bfloat16_as_ushort(ha) << 16;
            hi[reg + 1] |= (uint32_t)__bfloat16_as_ushort(hb) << 16;
            lo[reg]     |= (uint32_t)__bfloat16_as_ushort(la) << 16;
            lo[reg + 1] |= (uint32_t)__bfloat16_as_ushort(lb) << 16;
        }
    }
    const int base = ((g * 8 + ks) * 8 + mt) * 2;
    g_xa[(base + 0) * 32 + lane] = make_uint4(hi[0], hi[1], hi[2], hi[3]);
    g_xa[(base + 1) * 32 + lane] = make_uint4(lo[0], lo[1], lo[2], lo[3]);
}

// ---------------------------------------------------------------------------
// Kernel 2: Xsum[g][m] = sum_{k in group g} x[m][in_reorder[k]]
// ---------------------------------------------------------------------------
__global__ __launch_bounds__(256)
void xsum_kernel(const float* __restrict__ x, const int* __restrict__ in_reorder) {
    const int m    = blockIdx.x;
    const int tid  = threadIdx.x;
    const int g    = tid >> 3;
    const int part = tid & 7;
    float s = 0.f;
    #pragma unroll
    for (int j = 0; j < 16; j++)
        s += x[m * IN_F + __ldg(&in_reorder[g * 128 + part * 16 + j])];
    s += __shfl_xor_sync(0xffffffffu, s, 1);
    s += __shfl_xor_sync(0xffffffffu, s, 2);
    s += __shfl_xor_sync(0xffffffffu, s, 4);
    if (part == 0) g_xsum[g * 128 + m] = s;
}

// ---------------------------------------------------------------------------
// Kernel 3: repack 3 bit-planes -> nibbles in B-frag k-order, bank-swizzled:
// logical [tile][ks][qq(=r)][ow(=chunk)][it] written at chunk' = (ow+qq)&15.
// ---------------------------------------------------------------------------
__global__ __launch_bounds__(256)
void repack_kernel(const int* __restrict__ qweight, const int* __restrict__ offset) {
    const int t    = blockIdx.x * 256 + threadIdx.x;     // 2097152 threads
    const int it   = t & 3;
    const int ow   = (t >> 2) & 15;
    const int qq   = (t >> 6) & 3;
    const int ks   = (t >> 8) & 7;
    const int tile = t >> 11;                            // g*32 + nb
    const int kk   = 2 * qq + (it & 1) + ((it >> 1) << 3);
    const int i    = ks * 16 + kk;
    const int* src = qweight + __ldg(&offset[tile]);
    const int base = i * 4 + (ow >> 2);
    const int sh   = (ow & 3) * 8;
    const uint32_t b0 = ((uint32_t)__ldg(src + base)        >> sh) & 0xFFu;
    const uint32_t b1 = ((uint32_t)__ldg(src + base + 512)  >> sh) & 0xFFu;
    const uint32_t b2 = ((uint32_t)__ldg(src + base + 1024) >> sh) & 0xFFu;
    const int out = tile * 2048 + ks * 256 + qq * 64 + (((ow + qq) & 15) << 2) + it;
    g_qnib[out] = spread8(b0) | (spread8(b1) << 1) | (spread8(b2) << 2);
}

// ---------------------------------------------------------------------------
// Kernel 4: bf16 split-A GEMM; epilogue accT += a*S' + (a+b)*Xsum.
// grid (32 nb, 8 = mhalf*4+split), 256 thr, 2 CTA/SM, single full wave.
// ---------------------------------------------------------------------------
__global__ __launch_bounds__(256, 2)
void bcq_gemm_kernel(const float* __restrict__ alpha,
                     const float* __restrict__ beta)
{
    __shared__ uint32_t Qsm[2 * 2048];        // double-buffered B nibbles, 16 KB
    const int tid  = threadIdx.x;
    const int lane = tid & 31;
    const int wid  = tid >> 5;
    const int nb = blockIdx.x;
    const int mhalf = blockIdx.y >> 2;
    const int split = blockIdx.y & 3;
    const int wm = wid & 1;
    const int nq = wid >> 1;
    const uint32_t qsm_base = smem_u32(Qsm) + tid * 16;
    const int shv = (lane >> 2) * 4;
    const int r   = lane & 3;

    float accT[2][4][4];
    #pragma unroll
    for (int a = 0; a < 2; a++)
        #pragma unroll
        for (int b = 0; b < 4; b++)
            #pragma unroll
            for (int c = 0; c < 4; c++) accT[a][b][c] = 0.f;

    // prologue: group 0 B tile (8 KB = 256 thr x 32 B)
    {
        const uint32_t* src = g_qnib + (size_t)((split * 8) * 32 + nb) * 2048 + tid * 4;
        cp_async16(qsm_base,        src);
        cp_async16(qsm_base + 4096, src + 1024);
        CP_COMMIT();
    }

    for (int gi = 0; gi < 8; gi++) {
        const int g = split * 8 + gi;

        CP_WAIT0();
        __syncthreads();

        if (gi < 7) {
            const uint32_t* src = g_qnib + (size_t)((g + 1) * 32 + nb) * 2048 + tid * 4;
            const uint32_t d = qsm_base + ((gi + 1) & 1) * 8192;
            cp_async16(d,        src);
            cp_async16(d + 4096, src + 1024);
            CP_COMMIT();
        }

        const uint32_t* Qh = Qsm + (gi & 1) * 2048;

        float accS[2][4][4];
        #pragma unroll
        for (int a = 0; a < 2; a++)
            #pragma unroll
            for (int b = 0; b < 4; b++)
                #pragma unroll
                for (int c = 0; c < 4; c++) accS[a][b][c] = 0.f;

        #pragma unroll 2
        for (int ks = 0; ks < 8; ks++) {
            // --- A frags: hi+lo, 4 x LDG.128 (L2-resident, frag-ordered) ---
            uint32_t Ah[2][4], Al[2][4];
            #pragma unroll
            for (int mt = 0; mt < 2; mt++) {
                const int mtile = mhalf * 4 + wm * 2 + mt;
                const int base = ((g * 8 + ks) * 8 + mtile) * 2;
                const uint4 h = __ldg(&g_xa[(base + 0) * 32 + lane]);
                const uint4 l = __ldg(&g_xa[(base + 1) * 32 + lane]);
                Ah[mt][0] = h.x; Ah[mt][1] = h.y; Ah[mt][2] = h.z; Ah[mt][3] = h.w;
                Al[mt][0] = l.x; Al[mt][1] = l.y; Al[mt][2] = l.z; Al[mt][3] = l.w;
            }

            // --- B frags: bank-swizzled chunk (c + r) & 15 -> conflict-free ---
            uint32_t B[4][2];
            #pragma unroll
            for (int nt = 0; nt < 4; nt++) {
                const uint4 w = *(const uint4*)
                    (Qh + (((ks * 4 + r) << 4) + ((nq * 4 + nt + r) & 15)) * 4);
                B[nt][0] = bf16x2(nib2q(w.y, shv), nib2q(w.x, shv)); // {k0,k1}
                B[nt][1] = bf16x2(nib2q(w.w, shv), nib2q(w.z, shv)); // {k8,k9}
            }

            // --- 16 bf16 HMMA per warp per kstep (hi + lo, same acc) ---
            #pragma unroll
            for (int mt = 0; mt < 2; mt++)
                #pragma unroll
                for (int nt = 0; nt < 4; nt++) {
                    asm volatile(
                        "mma.sync.aligned.m16n8k16.row.col.f32.bf16.bf16.f32 "
                        "{%0,%1,%2,%3}, {%4,%5,%6,%7}, {%8,%9}, {%0,%1,%2,%3};"
                        : "+f"(accS[mt][nt][0]), "+f"(accS[mt][nt][1]),
                          "+f"(accS[mt][nt][2]), "+f"(accS[mt][nt][3])
                        : "r"(Ah[mt][0]), "r"(Ah[mt][1]), "r"(Ah[mt][2]), "r"(Ah[mt][3]),
                          "r"(B[nt][0]), "r"(B[nt][1]));
                    asm volatile(
                        "mma.sync.aligned.m16n8k16.row.col.f32.bf16.bf16.f32 "
                        "{%0,%1,%2,%3}, {%4,%5,%6,%7}, {%8,%9}, {%0,%1,%2,%3};"
                        : "+f"(accS[mt][nt][0]), "+f"(accS[mt][nt][1]),
                          "+f"(accS[mt][nt][2]), "+f"(accS[mt][nt][3])
                        : "r"(Al[mt][0]), "r"(Al[mt][1]), "r"(Al[mt][2]), "r"(Al[mt][3]),
                          "r"(B[nt][0]), "r"(B[nt][1]));
                }
        }

        // --- group epilogue (loads HERE: short live range, no MMA-loop regs) ---
        #pragma unroll
        for (int nt = 0; nt < 4; nt++) {
            const int col = nb * 128 + nq * 32 + nt * 8 + (lane & 3) * 2;
            float a0 = __ldg(&alpha[g * OUT_F + col]);
            float a1 = __ldg(&alpha[g * OUT_F + col + 1]);
            float c0 = a0 + __ldg(&beta[g * OUT_F + col]);       // (alpha+beta)
            float c1 = a1 + __ldg(&beta[g * OUT_F + col + 1]);
            #pragma unroll
            for (int mt = 0; mt < 2; mt++) {
                const int row = mhalf * 64 + wm * 32 + mt * 16 + (lane >> 2);
                const float x0 = __ldg(&g_xsum[g * 128 + row]);
                const float x1 = __ldg(&g_xsum[g * 128 + row + 8]);
                accT[mt][nt][0] = fmaf(a0, accS[mt][nt][0],
                                  fmaf(c0, x0, accT[mt][nt][0]));
                accT[mt][nt][1] = fmaf(a1, accS[mt][nt][1],
                                  fmaf(c1, x0, accT[mt][nt][1]));
                accT[mt][nt][2] = fmaf(a0, accS[mt][nt][2],
                                  fmaf(c0, x1, accT[mt][nt][2]));
                accT[mt][nt][3] = fmaf(a1, accS[mt][nt][3],
                                  fmaf(c1, x1, accT[mt][nt][3]));
            }
        }
    }

    // --- write K-split partials (deterministic) ---
    float* dst = g_t_part + (size_t)split * (M_TOK * OUT_F);
    #pragma unroll
    for (int mt = 0; mt < 2; mt++) {
        const int row0 = mhalf * 64 + wm * 32 + mt * 16 + (lane >> 2);
        #pragma unroll
        for (int nt = 0; nt < 4; nt++) {
            const int col = nb * 128 + nq * 32 + nt * 8 + (lane & 3) * 2;
            *(float2*)&dst[ row0      * OUT_F + col] =
                make_float2(accT[mt][nt][0], accT[mt][nt][1]);
            *(float2*)&dst[(row0 + 8) * OUT_F + col] =
                make_float2(accT[mt][nt][2], accT[mt][nt][3]);
        }
    }
}

// ---------------------------------------------------------------------------
// Kernel 5: reduce 4 planes (coalesced float4)
// ---------------------------------------------------------------------------
__global__ __launch_bounds__(256)
void reduce_kernel() {
    const int i = blockIdx.x * 256 + threadIdx.x;        // 131072 float4s
    const float4* p = (const float4*)g_t_part;
    float4 s = p[i];
    #pragma unroll
    for (int pl = 1; pl < NPLANE; pl++) {
        const float4 t = p[pl * 131072 + i];
        s.x += t.x; s.y += t.y; s.z += t.z; s.w += t.w;
    }
    ((float4*)g_t_sum)[i] = s;
}

// ---------------------------------------------------------------------------
// Kernel 6: output permutation — coalesced writes, 4 independent gathers
// ---------------------------------------------------------------------------
__global__ __launch_bounds__(256)
void permute_kernel(const int* __restrict__ out_reorder, float* __restrict__ y) {
    const int t = blockIdx.x * 256 + threadIdx.x;        // 131072
    const int c = t & 4095;
    const int mq = t >> 12;                              // 0..31
    const int n = __ldg(&out_reorder[c]);
    #pragma unroll
    for (int u = 0; u < 4; u++) {
        const int m = mq * 4 + u;
        y[(size_t)m * OUT_F + c] = g_t_sum[(m << 12) | n];
    }
}

// ---------------------------------------------------------------------------
// Launch
// ---------------------------------------------------------------------------
extern "C" void kernel_launch(void* const* d_in, const int* in_sizes, int n_in,
                              void* d_out, int out_size) {
    const float* x           = (const float*)d_in[0];
    const int*   qweight     = (const int*)  d_in[1];
    const float* alpha       = (const float*)d_in[2];
    const float* beta        = (const float*)d_in[3];
    // d_in[4] = block_bitwidth (uniform 3, unused)
    const int*   offset      = (const int*)  d_in[5];
    const int*   in_reorder  = (const int*)  d_in[6];
    const int*   out_reorder = (const int*)  d_in[7];
    float* y = (float*)d_out;

    prep_x_kernel<<<256, 256>>>(x, in_reorder);
    xsum_kernel<<<128, 256>>>(x, in_reorder);
    repack_kernel<<<8192, 256>>>(qweight, offset);
    bcq_gemm_kernel<<<dim3(32, 8), 256>>>(alpha, beta);
    reduce_kernel<<<512, 256>>>();
    permute_kernel<<<512, 256>>>(out_reorder, y);
}

// round 11
// speedup vs baseline: 1.6260x; 1.3980x over previous
#include <cuda_runtime.h>
#include <cuda_fp16.h>
#include <cstdint>

// ============================================================================
// BCQLinear: y = (x[:, in_reorder] @ dequant(qweight))[:, out_reorder]
// M=128, K=N=4096, WBITS=3, GS=OFI=128.
// R11: fp16 single-term MMA (11-bit mantissa == tf32, which passed at 2.95e-4),
//   PRMT-LUT dequant (q' = 2v-8 fp16 has lo-byte 0x00 -> one __byte_perm per
//   B reg), byte-layout B smem: ONE conflict-free LDS.128 per thread-kstep.
//   y = sum_g [ a*S' + (a+b)*Xsum ],  S' = x_f16 @ q',  q = q'+1 compensated.
// ============================================================================

#define M_TOK   128
#define IN_F    4096
#define OUT_F   4096
#define NGRP    32
#define NPLANE  4

// Scratch (static __device__ — no allocations)
__device__ uint4    g_xa[NGRP * 8 * 8 * 32];             // 1 MB  A frags (fp16)
__device__ uint32_t g_qb[1024 * 4096];                   // 16 MB B bytes, frag order
__device__ float    g_xsum[NGRP * M_TOK];                // 16 KB group row-sums
__device__ float    g_t_part[NPLANE * M_TOK * OUT_F];    // 8 MB  K-split partials
__device__ float    g_t_sum[M_TOK * OUT_F];              // 2 MB  reduced sum

__device__ __forceinline__ uint32_t smem_u32(const void* p) {
    uint32_t a;
    asm("{ .reg .u64 t; cvta.to.shared.u64 t, %1; cvt.u32.u64 %0, t; }"
        : "=r"(a) : "l"(p));
    return a;
}
__device__ __forceinline__ void cp_async16(uint32_t saddr, const void* gptr) {
    asm volatile("cp.async.cg.shared.global [%0], [%1], 16;"
                 :: "r"(saddr), "l"(gptr));
}
#define CP_COMMIT() asm volatile("cp.async.commit_group;" ::: "memory")
#define CP_WAIT0()  asm volatile("cp.async.wait_group 0;" ::: "memory")

// spread 8 bits so bit t lands at bit 4t
__device__ __forceinline__ uint32_t spread8(uint32_t x) {
    x = (x | (x << 12)) & 0x000F000Fu;
    x = (x | (x << 6))  & 0x03030303u;
    x = (x | (x << 3))  & 0x11111111u;
    return x;
}

// fp16 LUT for q' = 2v-8, v=0..7: {-8,-6,-4,-2,0,2,4,6}
//   hi bytes: C8 C6 C4 C0 | 00 40 44 46 ; lo bytes all 0x00.
#define QLUT_A 0xC0C4C6C8u
#define QLUT_B 0x46444000u

// ---------------------------------------------------------------------------
// Kernel 1: gather x[:, in_reorder] -> fp16 A fragments (m16n8k16).
// g_xa[((g*8+ks)*8+mtile)*32 + lane] = {a0,a1,a2,a3}
// ---------------------------------------------------------------------------
__global__ __launch_bounds__(256)
void prep_x_kernel(const float* __restrict__ x, const int* __restrict__ in_reorder) {
    const int t    = blockIdx.x * 256 + threadIdx.x;     // 65536 threads
    const int lane = t & 31;
    const int mt   = (t >> 5) & 7;
    const int ks   = (t >> 8) & 7;
    const int g    = t >> 11;
    const int r0   = mt * 16 + (lane >> 2);
    const int kb   = g * 128 + ks * 16 + (lane & 3) * 2;
    const int kk[4] = { kb, kb + 1, kb + 8, kb + 9 };
    uint32_t hi[4] = {0, 0, 0, 0};
    #pragma unroll
    for (int j = 0; j < 4; j++) {
        const int p = __ldg(&in_reorder[kk[j]]);
        const __half ha = __float2half_rn(x[ r0      * IN_F + p]);
        const __half hb = __float2half_rn(x[(r0 + 8) * IN_F + p]);
        const int reg = (j >> 1) * 2;
        const int sh  = (j & 1) * 16;
        hi[reg]     |= (uint32_t)__half_as_ushort(ha) << sh;
        hi[reg + 1] |= (uint32_t)__half_as_ushort(hb) << sh;
    }
    g_xa[((g * 8 + ks) * 8 + mt) * 32 + lane] = make_uint4(hi[0], hi[1], hi[2], hi[3]);
}

// ---------------------------------------------------------------------------
// Kernel 2: Xsum[g][m] = sum_{k in group g} x[m][in_reorder[k]]
// ---------------------------------------------------------------------------
__global__ __launch_bounds__(256)
void xsum_kernel(const float* __restrict__ x, const int* __restrict__ in_reorder) {
    const int m    = blockIdx.x;
    const int tid  = threadIdx.x;
    const int g    = tid >> 3;
    const int part = tid & 7;
    float s = 0.f;
    #pragma unroll
    for (int j = 0; j < 16; j++)
        s += x[m * IN_F + __ldg(&in_reorder[g * 128 + part * 16 + j])];
    s += __shfl_xor_sync(0xffffffffu, s, 1);
    s += __shfl_xor_sync(0xffffffffu, s, 2);
    s += __shfl_xor_sync(0xffffffffu, s, 4);
    if (part == 0) g_xsum[g * 128 + m] = s;
}

// ---------------------------------------------------------------------------
// Kernel 3: repack bit-planes -> BYTE layout in B-frag order.
// Word at [tile][chunk16][nt]: bytes [k0,k1,k8,k9] (each = 3-bit code v)
// for col c = nq*32 + nt*8 + o,  k pattern {2r,2r+1,2r+8,2r+9} in kstep ks.
// chunk16 = ((ks*4+r)*8+o)*4 + ((nq+r)&3)   (swizzle: 32 lanes distinct mod 32)
// Thread = (tile, ks, r, nq): 131072 threads, 12 LDG, 8 STG.128.
// ---------------------------------------------------------------------------
__global__ __launch_bounds__(256)
void repack_kernel(const int* __restrict__ qweight, const int* __restrict__ offset) {
    const int t    = blockIdx.x * 256 + threadIdx.x;     // 131072
    const int nq   = t & 3;
    const int r    = (t >> 2) & 3;
    const int ks   = (t >> 4) & 7;
    const int tile = t >> 7;                             // g*32 + nb
    const int* src = qweight + __ldg(&offset[tile]);

    uint32_t p0[4], p1[4], p2[4];
    #pragma unroll
    for (int ki = 0; ki < 4; ki++) {
        const int i    = ks * 16 + 2 * r + (ki & 1) + ((ki >> 1) << 3);
        const int widx = i * 4 + nq;
        p0[ki] = (uint32_t)__ldg(src + widx);
        p1[ki] = (uint32_t)__ldg(src + widx + 512);
        p2[ki] = (uint32_t)__ldg(src + widx + 1024);
    }
    // nib[nt][ki]: 8 nibbles over o (nibble o = v for (o, nt, ki))
    uint32_t nib[4][4];
    #pragma unroll
    for (int nt = 0; nt < 4; nt++)
        #pragma unroll
        for (int ki = 0; ki < 4; ki++)
            nib[nt][ki] = spread8((p0[ki] >> (nt * 8)) & 0xFFu)
                        | (spread8((p1[ki] >> (nt * 8)) & 0xFFu) << 1)
                        | (spread8((p2[ki] >> (nt * 8)) & 0xFFu) << 2);

    uint4* dst = ((uint4*)g_qb) + tile * 1024;
    const int cbase = (((ks * 4 + r) * 8) << 2) + ((nq + r) & 3);
    #pragma unroll
    for (int o = 0; o < 8; o++) {
        uint32_t wds[4];
        #pragma unroll
        for (int nt = 0; nt < 4; nt++)
            wds[nt] = ((nib[nt][0] >> (4 * o)) & 0xFu)
                    | (((nib[nt][1] >> (4 * o)) & 0xFu) << 8)
                    | (((nib[nt][2] >> (4 * o)) & 0xFu) << 16)
                    | (((nib[nt][3] >> (4 * o)) & 0xFu) << 24);
        dst[cbase + o * 4] = make_uint4(wds[0], wds[1], wds[2], wds[3]);
    }
}

// ---------------------------------------------------------------------------
// Kernel 4: fp16 GEMM; epilogue accT += a*S' + (a+b)*Xsum.
// grid (32 nb, 8 = mhalf*4+split), 256 thr, 2 CTA/SM, single full wave.
// Per thread-kstep: 2 A LDG.128 + 1 B LDS.128 + 2 PRMT-dequants x4 + 8 HMMA.
// ---------------------------------------------------------------------------
__global__ __launch_bounds__(256, 2)
void bcq_gemm_kernel(const float* __restrict__ alpha,
                     const float* __restrict__ beta)
{
    __shared__ uint32_t Qsm[2 * 4096];        // double-buffered B bytes, 32 KB
    const int tid  = threadIdx.x;
    const int lane = tid & 31;
    const int wid  = tid >> 5;
    const int nb = blockIdx.x;
    const int mhalf = blockIdx.y >> 2;
    const int split = blockIdx.y & 3;
    const int wm = wid & 1;
    const int nq = wid >> 1;
    const uint32_t qsm_base = smem_u32(Qsm) + tid * 16;
    const int r = lane & 3, o = lane >> 2;
    // conflict-free chunk: distinct mod 32 across the warp
    const int boffw = (((r * 8 + o) << 2) + ((nq + r) & 3)) << 2;  // word offset

    float accT[2][4][4];
    #pragma unroll
    for (int a = 0; a < 2; a++)
        #pragma unroll
        for (int b = 0; b < 4; b++)
            #pragma unroll
            for (int c = 0; c < 4; c++) accT[a][b][c] = 0.f;

    // prologue: group 0 B tile (16 KB = 256 thr x 64 B)
    {
        const uint32_t* src = g_qb + (size_t)((split * 8) * 32 + nb) * 4096 + tid * 4;
        cp_async16(qsm_base,         src);
        cp_async16(qsm_base + 4096,  src + 1024);
        cp_async16(qsm_base + 8192,  src + 2048);
        cp_async16(qsm_base + 12288, src + 3072);
        CP_COMMIT();
    }

    for (int gi = 0; gi < 8; gi++) {
        const int g = split * 8 + gi;

        CP_WAIT0();
        __syncthreads();

        if (gi < 7) {
            const uint32_t* src = g_qb + (size_t)((g + 1) * 32 + nb) * 4096 + tid * 4;
            const uint32_t d = qsm_base + ((gi + 1) & 1) * 16384;
            cp_async16(d,         src);
            cp_async16(d + 4096,  src + 1024);
            cp_async16(d + 8192,  src + 2048);
            cp_async16(d + 12288, src + 3072);
            CP_COMMIT();
        }

        const uint32_t* Qh = Qsm + (gi & 1) * 4096;

        float accS[2][4][4];
        #pragma unroll
        for (int a = 0; a < 2; a++)
            #pragma unroll
            for (int b = 0; b < 4; b++)
                #pragma unroll
                for (int c = 0; c < 4; c++) accS[a][b][c] = 0.f;

        #pragma unroll 4
        for (int ks = 0; ks < 8; ks++) {
            // --- A frags: fp16, 2 x LDG.128 (L2-resident, frag-ordered) ---
            uint32_t A[2][4];
            #pragma unroll
            for (int mt = 0; mt < 2; mt++) {
                const int mtile = mhalf * 4 + wm * 2 + mt;
                const uint4 h = __ldg(&g_xa[((g * 8 + ks) * 8 + mtile) * 32 + lane]);
                A[mt][0] = h.x; A[mt][1] = h.y; A[mt][2] = h.z; A[mt][3] = h.w;
            }

            // --- B: ONE LDS.128 -> 4 words (nt), bytes [k0,k1,k8,k9] ---
            const uint4 w = *(const uint4*)(Qh + ks * 512 + boffw);
            const uint32_t wn[4] = {w.x, w.y, w.z, w.w};

            // --- dequant: selector = ((w<<4)&0xF0F0)|0x0404, one PRMT each ---
            uint32_t B[4][2];
            #pragma unroll
            for (int nt = 0; nt < 4; nt++) {
                B[nt][0] = __byte_perm(QLUT_A, QLUT_B,
                                       ((wn[nt] << 4)  & 0xF0F0u) | 0x0404u);
                B[nt][1] = __byte_perm(QLUT_A, QLUT_B,
                                       ((wn[nt] >> 12) & 0xF0F0u) | 0x0404u);
            }

            // --- 8 fp16 HMMA per warp per kstep ---
            #pragma unroll
            for (int mt = 0; mt < 2; mt++)
                #pragma unroll
                for (int nt = 0; nt < 4; nt++)
                    asm volatile(
                        "mma.sync.aligned.m16n8k16.row.col.f32.f16.f16.f32 "
                        "{%0,%1,%2,%3}, {%4,%5,%6,%7}, {%8,%9}, {%0,%1,%2,%3};"
                        : "+f"(accS[mt][nt][0]), "+f"(accS[mt][nt][1]),
                          "+f"(accS[mt][nt][2]), "+f"(accS[mt][nt][3])
                        : "r"(A[mt][0]), "r"(A[mt][1]), "r"(A[mt][2]), "r"(A[mt][3]),
                          "r"(B[nt][0]), "r"(B[nt][1]));
        }

        // --- group epilogue: accT += alpha*S' + (alpha+beta)*Xsum ---
        #pragma unroll
        for (int nt = 0; nt < 4; nt++) {
            const int col = nb * 128 + nq * 32 + nt * 8 + (lane & 3) * 2;
            float a0 = __ldg(&alpha[g * OUT_F + col]);
            float a1 = __ldg(&alpha[g * OUT_F + col + 1]);
            float c0 = a0 + __ldg(&beta[g * OUT_F + col]);
            float c1 = a1 + __ldg(&beta[g * OUT_F + col + 1]);
            #pragma unroll
            for (int mt = 0; mt < 2; mt++) {
                const int row = mhalf * 64 + wm * 32 + mt * 16 + (lane >> 2);
                const float x0 = __ldg(&g_xsum[g * 128 + row]);
                const float x1 = __ldg(&g_xsum[g * 128 + row + 8]);
                accT[mt][nt][0] = fmaf(a0, accS[mt][nt][0],
                                  fmaf(c0, x0, accT[mt][nt][0]));
                accT[mt][nt][1] = fmaf(a1, accS[mt][nt][1],
                                  fmaf(c1, x0, accT[mt][nt][1]));
                accT[mt][nt][2] = fmaf(a0, accS[mt][nt][2],
                                  fmaf(c0, x1, accT[mt][nt][2]));
                accT[mt][nt][3] = fmaf(a1, accS[mt][nt][3],
                                  fmaf(c1, x1, accT[mt][nt][3]));
            }
        }
    }

    // --- write K-split partials (deterministic) ---
    float* dst = g_t_part + (size_t)split * (M_TOK * OUT_F);
    #pragma unroll
    for (int mt = 0; mt < 2; mt++) {
        const int row0 = mhalf * 64 + wm * 32 + mt * 16 + (lane >> 2);
        #pragma unroll
        for (int nt = 0; nt < 4; nt++) {
            const int col = nb * 128 + nq * 32 + nt * 8 + (lane & 3) * 2;
            *(float2*)&dst[ row0      * OUT_F + col] =
                make_float2(accT[mt][nt][0], accT[mt][nt][1]);
            *(float2*)&dst[(row0 + 8) * OUT_F + col] =
                make_float2(accT[mt][nt][2], accT[mt][nt][3]);
        }
    }
}

// ---------------------------------------------------------------------------
// Kernel 5: reduce 4 planes (coalesced float4)
// ---------------------------------------------------------------------------
__global__ __launch_bounds__(256)
void reduce_kernel() {
    const int i = blockIdx.x * 256 + threadIdx.x;        // 131072 float4s
    const float4* p = (const float4*)g_t_part;
    float4 s = p[i];
    #pragma unroll
    for (int pl = 1; pl < NPLANE; pl++) {
        const float4 t = p[pl * 131072 + i];
        s.x += t.x; s.y += t.y; s.z += t.z; s.w += t.w;
    }
    ((float4*)g_t_sum)[i] = s;
}

// ---------------------------------------------------------------------------
// Kernel 6: output permutation — coalesced writes, 4 independent gathers
// ---------------------------------------------------------------------------
__global__ __launch_bounds__(256)
void permute_kernel(const int* __restrict__ out_reorder, float* __restrict__ y) {
    const int t = blockIdx.x * 256 + threadIdx.x;        // 131072
    const int c = t & 4095;
    const int mq = t >> 12;                              // 0..31
    const int n = __ldg(&out_reorder[c]);
    #pragma unroll
    for (int u = 0; u < 4; u++) {
        const int m = mq * 4 + u;
        y[(size_t)m * OUT_F + c] = g_t_sum[(m << 12) | n];
    }
}

// ---------------------------------------------------------------------------
// Launch
// ---------------------------------------------------------------------------
extern "C" void kernel_launch(void* const* d_in, const int* in_sizes, int n_in,
                              void* d_out, int out_size) {
    const float* x           = (const float*)d_in[0];
    const int*   qweight     = (const int*)  d_in[1];
    const float* alpha       = (const float*)d_in[2];
    const float* beta        = (const float*)d_in[3];
    // d_in[4] = block_bitwidth (uniform 3, unused)
    const int*   offset      = (const int*)  d_in[5];
    const int*   in_reorder  = (const int*)  d_in[6];
    const int*   out_reorder = (const int*)  d_in[7];
    float* y = (float*)d_out;

    prep_x_kernel<<<256, 256>>>(x, in_reorder);
    xsum_kernel<<<128, 256>>>(x, in_reorder);
    repack_kernel<<<512, 256>>>(qweight, offset);
    bcq_gemm_kernel<<<dim3(32, 8), 256>>>(alpha, beta);
    reduce_kernel<<<512, 256>>>();
    permute_kernel<<<512, 256>>>(out_reorder, y);
}